// round 15
// baseline (speedup 1.0000x reference)
#include <cuda_runtime.h>
#include <cuda_bf16.h>
#include <cstdint>

#define B_ 128
#define T_ 2048
#define TT 64
#define NTILES 32
#define QSTR 132
#define NTHR 512

// smem word offsets
#define WSH_OFF 0                          // 32768: W bf16, swizzled
#define Q0_OFF  32768                      // 8448
#define Q1_OFF  (Q0_OFF + TT * QSTR)       // 41216
#define WG_OFF  (Q1_OFF + TT * QSTR)       // 49664: float2 {w,gpr} x256
#define AP_OFF  (WG_OFF + 512)             // 50176: ap[64][8]
#define RED_OFF (AP_OFF + 512)             // 50688: 16
#define ZB_OFF  (RED_OFF + 16)             // 50704: zbuf[8][256] (ph[512] in prologue)
#define SMEM_WORDS (ZB_OFF + 2048)

__device__ __forceinline__ float fast_tanh(float x) {
    float y;
    asm("tanh.approx.f32 %0, %1;" : "=f"(y) : "f"(x));
    return y;
}

__global__ __launch_bounds__(NTHR, 1)
void kFused(const float* __restrict__ input_q,
            const float* __restrict__ W_q,
            const float* __restrict__ wvec,
            const float* __restrict__ match_b,
            const int* __restrict__ mask_q,
            const float* __restrict__ input_p,
            const float* __restrict__ h_tm1,
            const float* __restrict__ W_p_r,
            const float* __restrict__ b_p_r,
            const float* __restrict__ b_q,
            float* __restrict__ out) {
    extern __shared__ uint32_t sh[];
    uint32_t* Wsh  = sh + WSH_OFF;
    uint32_t* Qsh0 = sh + Q0_OFF;
    uint32_t* Qsh1 = sh + Q1_OFF;
    float2* wg_sh = reinterpret_cast<float2*>(sh + WG_OFF);
    float*  ap_sh = reinterpret_cast<float*>(sh + AP_OFF);
    float*  red   = reinterpret_cast<float*>(sh + RED_OFF);
    float*  zbuf  = reinterpret_cast<float*>(sh + ZB_OFF);

    int b    = blockIdx.x;
    int tid  = threadIdx.x;
    int lane = tid & 31, wid = tid >> 5;

    // ================= Prologue =================
    float* ph = zbuf;                       // [512] = [input_p | h_tm1]
    if (tid < 256) ph[tid] = input_p[b * 256 + tid];
    else           ph[tid] = h_tm1[b * 256 + (tid - 256)];
    __syncthreads();

    // gpr: 16 warps x 16 rows (warp-coalesced dot)
    for (int r = 0; r < 16; ++r) {
        int d = wid * 16 + r;
        const float4* row = reinterpret_cast<const float4*>(W_p_r + (size_t)d * 512);
        const float4* p4  = reinterpret_cast<const float4*>(ph);
        float acc = 0.f;
#pragma unroll
        for (int i = 0; i < 4; ++i) {
            float4 wv = row[i * 32 + lane];
            float4 pv = p4[i * 32 + lane];
            acc += wv.x * pv.x + wv.y * pv.y + wv.z * pv.z + wv.w * pv.w;
        }
#pragma unroll
        for (int o = 16; o; o >>= 1) acc += __shfl_xor_sync(0xffffffffu, acc, o);
        if (lane == 0) wg_sh[d] = make_float2(wvec[d], acc + b_p_r[d] + b_q[d]);
    }

    // W_q -> bf16 smem, 16B-chunk XOR swizzle
    for (int i = tid; i < 256 * 128; i += NTHR) {
        int n = i >> 7, kw = i & 127;
        float2 f = reinterpret_cast<const float2*>(W_q)[n * 128 + kw];
        __nv_bfloat162 h = __floats2bfloat162_rn(f.x, f.y);
        int phys = (kw >> 2) ^ (n & 7);
        Wsh[n * 128 + phys * 4 + (kw & 3)] = *reinterpret_cast<uint32_t*>(&h);
    }

    const float   mb  = match_b[0];
    const float4* qb4 = reinterpret_cast<const float4*>(input_q + (size_t)b * T_ * 256);
    const int*    mqb = mask_q + (size_t)b * T_;

    // ---- Preload tile 0 into Qsh0
#pragma unroll
    for (int j = 0; j < 8; ++j) {
        int idx = tid + j * NTHR;
        float4 f = qb4[idx];
        int row = idx >> 6, c4 = idx & 63;
        __nv_bfloat162 h0 = __floats2bfloat162_rn(f.x, f.y);
        __nv_bfloat162 h1 = __floats2bfloat162_rn(f.z, f.w);
        Qsh0[row * QSTR + c4 * 2]     = *reinterpret_cast<uint32_t*>(&h0);
        Qsh0[row * QSTR + c4 * 2 + 1] = *reinterpret_cast<uint32_t*>(&h1);
    }
    __syncthreads();

    // ================= Main loop =================
    int warp_m = wid & 1;        // 2 warps over 64 rows (32 each)
    int warp_n = wid >> 1;       // 8 warps over 256 cols (32 each)
    int q8    = wid >> 1;        // t-eighth this warp handles (8 tokens); 2 warps redundant e
    int tbase = q8 * 8;
    int pair  = tid & 63;        // uint2 d-pair (4 douts: 4*pair .. 4*pair+3)

    float Sth = 0.f, Mth = -1e30f;         // even warps, lanes 0..7
    float z0 = 0.f, z1 = 0.f, z2 = 0.f, z3 = 0.f;

    for (int it = 0; it < NTILES; ++it) {
        uint32_t* Qcur = (it & 1) ? Qsh1 : Qsh0;
        uint32_t* Qnxt = (it & 1) ? Qsh0 : Qsh1;
        int t0 = it * TT;

        // ---- prefetch: mask for this warp's tokens + Q for next tile
        int mreg = (lane < 8) ? mqb[t0 + tbase + lane] : 0;
        bool has_next = (it + 1 < NTILES);
        float4 pf[8];
        if (has_next) {
            const float4* src = qb4 + (size_t)(t0 + TT) * 64;
#pragma unroll
            for (int j = 0; j < 8; ++j) pf[j] = src[tid + j * NTHR];
        }

        // ---- MMA: C[64 x 256] = Qtile @ W^T, warp tile m32 x n32
        float c[8][4];
#pragma unroll
        for (int q = 0; q < 8; ++q) { c[q][0] = c[q][1] = c[q][2] = c[q][3] = 0.f; }

#pragma unroll 4
        for (int kc = 0; kc < 16; ++kc) {
            uint32_t a[2][4];
#pragma unroll
            for (int mt = 0; mt < 2; ++mt) {
                int arow = warp_m * 32 + mt * 16 + (lane & 15);
                int acol = kc * 8 + ((lane & 16) ? 4 : 0);
                uint32_t aaddr = (uint32_t)__cvta_generic_to_shared(&Qcur[arow * QSTR + acol]);
                asm volatile("ldmatrix.sync.aligned.m8n8.x4.shared.b16 {%0,%1,%2,%3}, [%4];"
                             : "=r"(a[mt][0]), "=r"(a[mt][1]), "=r"(a[mt][2]), "=r"(a[mt][3])
                             : "r"(aaddr));
            }
#pragma unroll
            for (int np = 0; np < 2; ++np) {
                int row   = warp_n * 32 + np * 16 + (lane & 7) + ((lane & 16) ? 8 : 0);
                int chunk = kc * 2 + ((lane & 8) ? 1 : 0);
                int phys  = chunk ^ (row & 7);
                uint32_t baddr = (uint32_t)__cvta_generic_to_shared(&Wsh[row * 128 + phys * 4]);
                uint32_t b0, b1, b2, b3;
                asm volatile("ldmatrix.sync.aligned.m8n8.x4.shared.b16 {%0,%1,%2,%3}, [%4];"
                             : "=r"(b0), "=r"(b1), "=r"(b2), "=r"(b3) : "r"(baddr));
#pragma unroll
                for (int mt = 0; mt < 2; ++mt) {
                    float* c0 = c[mt * 4 + np * 2];
                    float* c1 = c[mt * 4 + np * 2 + 1];
                    asm volatile(
                        "mma.sync.aligned.m16n8k16.row.col.f32.bf16.bf16.f32 "
                        "{%0,%1,%2,%3}, {%4,%5,%6,%7}, {%8,%9}, {%0,%1,%2,%3};"
                        : "+f"(c0[0]), "+f"(c0[1]), "+f"(c0[2]), "+f"(c0[3])
                        : "r"(a[mt][0]), "r"(a[mt][1]), "r"(a[mt][2]), "r"(a[mt][3]),
                          "r"(b0), "r"(b1));
                    asm volatile(
                        "mma.sync.aligned.m16n8k16.row.col.f32.bf16.bf16.f32 "
                        "{%0,%1,%2,%3}, {%4,%5,%6,%7}, {%8,%9}, {%0,%1,%2,%3};"
                        : "+f"(c1[0]), "+f"(c1[1]), "+f"(c1[2]), "+f"(c1[3])
                        : "r"(a[mt][0]), "r"(a[mt][1]), "r"(a[mt][2]), "r"(a[mt][3]),
                          "r"(b2), "r"(b3));
                }
            }
        }

        // ---- store prefetched tile into other buffer
        if (has_next) {
#pragma unroll
            for (int j = 0; j < 8; ++j) {
                int idx = tid + j * NTHR;
                int row = idx >> 6, c4 = idx & 63;
                __nv_bfloat162 h0 = __floats2bfloat162_rn(pf[j].x, pf[j].y);
                __nv_bfloat162 h1 = __floats2bfloat162_rn(pf[j].z, pf[j].w);
                Qnxt[row * QSTR + c4 * 2]     = *reinterpret_cast<uint32_t*>(&h0);
                Qnxt[row * QSTR + c4 * 2 + 1] = *reinterpret_cast<uint32_t*>(&h1);
            }
        }

        // ---- epilogue: tanh + dot(w), quad reduce, disjoint partial writes
#pragma unroll
        for (int mt = 0; mt < 2; ++mt) {
            float p0 = 0.f, p1 = 0.f;
#pragma unroll
            for (int np = 0; np < 2; ++np) {
#pragma unroll
                for (int j = 0; j < 2; ++j) {
                    int n = warp_n * 32 + np * 16 + j * 8 + (lane & 3) * 2;
                    float4 wg = *reinterpret_cast<const float4*>(&wg_sh[n]);   // {w0,g0,w1,g1}
                    float* cc = c[mt * 4 + np * 2 + j];
                    p0 += wg.x * fast_tanh(cc[0] + wg.y) + wg.z * fast_tanh(cc[1] + wg.w);
                    p1 += wg.x * fast_tanh(cc[2] + wg.y) + wg.z * fast_tanh(cc[3] + wg.w);
                }
            }
            p0 += __shfl_xor_sync(0xffffffffu, p0, 1);
            p0 += __shfl_xor_sync(0xffffffffu, p0, 2);
            p1 += __shfl_xor_sync(0xffffffffu, p1, 1);
            p1 += __shfl_xor_sync(0xffffffffu, p1, 2);
            if ((lane & 3) == 0) {
                int row0 = warp_m * 32 + mt * 16 + (lane >> 2);
                ap_sh[row0 * 8 + warp_n]       = p0;
                ap_sh[(row0 + 8) * 8 + warp_n] = p1;
            }
        }
        __syncthreads();   // S1: ap ready, STS(Qnxt) done

        // ---- merged stage1 + z (warp-local, no extra barrier)
        float e8 = 0.f;
        if (lane < 8) {
            const float4* ap4 = reinterpret_cast<const float4*>(&ap_sh[(tbase + lane) * 8]);
            float4 apa = ap4[0], apb = ap4[1];
            float raw = ((apa.x + apa.y) + (apa.z + apa.w)) +
                        ((apb.x + apb.y) + (apb.z + apb.w)) + mb;
            float mflt = (float)mreg;
            float x = fminf(fmaxf(raw, -15.f), 15.f) * mflt;
            e8 = __expf(x - 15.f) * mflt;
            if ((wid & 1) == 0) { Sth += e8; Mth = fmaxf(Mth, x); }
        }
        {
            float a0 = 0.f, a1 = 0.f, a2 = 0.f, a3 = 0.f;
#pragma unroll
            for (int k = 0; k < 8; ++k) {
                float e = __shfl_sync(0xffffffffu, e8, k);
                int t = tbase + k;
                uint2 qw = *reinterpret_cast<const uint2*>(&Qcur[t * QSTR + pair * 2]);
                __nv_bfloat162 h0 = *reinterpret_cast<__nv_bfloat162*>(&qw.x);
                __nv_bfloat162 h1 = *reinterpret_cast<__nv_bfloat162*>(&qw.y);
                a0 += e * __bfloat162float(__low2bfloat16(h0));
                a1 += e * __bfloat162float(__high2bfloat16(h0));
                a2 += e * __bfloat162float(__low2bfloat16(h1));
                a3 += e * __bfloat162float(__high2bfloat16(h1));
            }
            z0 += a0; z1 += a1; z2 += a2; z3 += a3;
        }
        __syncthreads();   // S2: Qcur & ap reads done; Qnxt visible for next MMA
    }

    // ================= Final =================
    if (((wid & 1) == 0) && lane < 8) {
        float s = Sth, m = Mth;
#pragma unroll
        for (int o = 4; o; o >>= 1) {
            s += __shfl_xor_sync(0x000000FFu, s, o);
            m = fmaxf(m, __shfl_xor_sync(0x000000FFu, m, o));
        }
        if (lane == 0) { red[wid >> 1] = s; red[8 + (wid >> 1)] = m; }
    }
    zbuf[q8 * 256 + pair * 4 + 0] = z0;
    zbuf[q8 * 256 + pair * 4 + 1] = z1;
    zbuf[q8 * 256 + pair * 4 + 2] = z2;
    zbuf[q8 * 256 + pair * 4 + 3] = z3;
    __syncthreads();

    if (tid < 256) {
        float Sp = ((red[0] + red[1]) + (red[2] + red[3])) +
                   ((red[4] + red[5]) + (red[6] + red[7]));
        float Mg = fmaxf(fmaxf(fmaxf(red[8], red[9]), fmaxf(red[10], red[11])),
                         fmaxf(fmaxf(red[12], red[13]), fmaxf(red[14], red[15])));
        float denom = Sp + 1e-6f * __expf(Mg - 15.f);
        float zt = 0.f;
#pragma unroll
        for (int o = 0; o < 8; ++o) zt += zbuf[o * 256 + tid];
        out[b * 512 + tid]       = input_p[b * 256 + tid];
        out[b * 512 + 256 + tid] = zt / denom;
    }
}

extern "C" void kernel_launch(void* const* d_in, const int* in_sizes, int n_in,
                              void* d_out, int out_size) {
    const float* input_p = (const float*)d_in[0];
    const float* input_q = (const float*)d_in[2];
    const int*   mask_q  = (const int*)d_in[3];
    const float* h_tm1   = (const float*)d_in[4];
    const float* W_p_r   = (const float*)d_in[5];
    const float* b_p_r   = (const float*)d_in[6];
    const float* W_q     = (const float*)d_in[7];
    const float* b_q     = (const float*)d_in[8];
    const float* wv      = (const float*)d_in[9];
    const float* match_b = (const float*)d_in[10];
    float* out = (float*)d_out;

    size_t smemF = (size_t)SMEM_WORDS * 4;
    cudaFuncSetAttribute(kFused, cudaFuncAttributeMaxDynamicSharedMemorySize, (int)smemF);
    kFused<<<B_, NTHR, smemF>>>(input_q, W_q, wv, match_b, mask_q,
                                input_p, h_tm1, W_p_r, b_p_r, b_q, out);
}

// round 16
// speedup vs baseline: 1.0543x; 1.0543x over previous
#include <cuda_runtime.h>
#include <cuda_bf16.h>
#include <cstdint>

#define B_ 128
#define T_ 2048
#define TT 64
#define QSTR 132
#define NTHR 512
#define GRID 148
#define UNITS 4096     // 128 batches * 32 tiles

// smem word offsets
#define WSH_OFF 0                          // 32768: W bf16, swizzled
#define Q0_OFF  32768                      // 8448
#define Q1_OFF  (Q0_OFF + TT * QSTR)       // 41216
#define WG_OFF  (Q1_OFF + TT * QSTR)       // 49664: float2 {w,gpr} x256
#define E_OFF   (WG_OFF + 512)             // e[64]
#define AP_OFF  (E_OFF + 64)               // ap[64][8]
#define RED_OFF (AP_OFF + 512)             // 20 words (16 red + flag)
#define ZB_OFF  (RED_OFF + 20)             // zbuf[4][256] / ph[512]
#define SMEM_WORDS (ZB_OFF + 1024)

__device__ float g_pz[B_ * 4 * 256];       // z partial per (batch, slot)
__device__ float g_ps[B_ * 4 * 2];         // {S, M} per (batch, slot)
__device__ int   g_cnt[B_];                // arrival tickets (monotone; used mod count)

__device__ __forceinline__ float fast_tanh(float x) {
    float y;
    asm("tanh.approx.f32 %0, %1;" : "=f"(y) : "f"(x));
    return y;
}

__device__ __forceinline__ int unit_start(int i) {
    return (int)(((long long)i * UNITS) / GRID);
}
__device__ __forceinline__ int cta_of_unit(int u) {
    int i = (int)(((long long)u * GRID) / UNITS);   // floor guess: start(i) <= u
    while (unit_start(i + 1) <= u) ++i;
    return i;
}

__global__ __launch_bounds__(NTHR, 1)
void kFused(const float* __restrict__ input_q,
            const float* __restrict__ W_q,
            const float* __restrict__ wvec,
            const float* __restrict__ match_b,
            const int* __restrict__ mask_q,
            const float* __restrict__ input_p,
            const float* __restrict__ h_tm1,
            const float* __restrict__ W_p_r,
            const float* __restrict__ b_p_r,
            const float* __restrict__ b_q,
            float* __restrict__ out) {
    extern __shared__ uint32_t sh[];
    uint32_t* Wsh  = sh + WSH_OFF;
    uint32_t* Qsh0 = sh + Q0_OFF;
    uint32_t* Qsh1 = sh + Q1_OFF;
    float2* wg_sh = reinterpret_cast<float2*>(sh + WG_OFF);
    float*  e_sh  = reinterpret_cast<float*>(sh + E_OFF);
    float*  ap_sh = reinterpret_cast<float*>(sh + AP_OFF);
    float*  red   = reinterpret_cast<float*>(sh + RED_OFF);
    int*    flagp = reinterpret_cast<int*>(sh + RED_OFF + 16);
    float*  zbuf  = reinterpret_cast<float*>(sh + ZB_OFF);

    int cta  = blockIdx.x;
    int tid  = threadIdx.x;
    int lane = tid & 31, wid = tid >> 5;
    int u0 = unit_start(cta), u1 = unit_start(cta + 1);

    // ================= Prologue: W_q -> bf16 smem (XOR swizzle) =================
    for (int i = tid; i < 256 * 128; i += NTHR) {
        int n = i >> 7, kw = i & 127;
        float2 f = reinterpret_cast<const float2*>(W_q)[n * 128 + kw];
        __nv_bfloat162 h = __floats2bfloat162_rn(f.x, f.y);
        int phys = (kw >> 2) ^ (n & 7);
        Wsh[n * 128 + phys * 4 + (kw & 3)] = *reinterpret_cast<uint32_t*>(&h);
    }

    const float mb = match_b[0];

    // preload first unit's Q tile into buffer (u0 & 1)
    {
        int b0 = u0 >> 5, it0 = u0 & 31;
        const float4* src = reinterpret_cast<const float4*>(input_q) +
                            (size_t)b0 * T_ * 64 + (size_t)it0 * TT * 64;
        uint32_t* Qdst = (u0 & 1) ? Qsh1 : Qsh0;
#pragma unroll
        for (int j = 0; j < 8; ++j) {
            int idx = tid + j * NTHR;
            float4 f = src[idx];
            int row = idx >> 6, c4 = idx & 63;
            __nv_bfloat162 h0 = __floats2bfloat162_rn(f.x, f.y);
            __nv_bfloat162 h1 = __floats2bfloat162_rn(f.z, f.w);
            Qdst[row * QSTR + c4 * 2]     = *reinterpret_cast<uint32_t*>(&h0);
            Qdst[row * QSTR + c4 * 2 + 1] = *reinterpret_cast<uint32_t*>(&h1);
        }
    }
    __syncthreads();

    // ================= Unit loop =================
    int warp_m = wid & 1;
    int warp_n = wid >> 1;
    int zq = wid >> 2;
    int d0 = (tid & 127) * 2;
    int zword = tid & 127;

    float Sth = 0.f, Mth = -1e30f;
    float z0 = 0.f, z1 = 0.f;

    for (int u = u0; u < u1; ++u) {
        int b  = u >> 5;
        int it = u & 31;

        // ---- batch setup (gpr) at batch entry ----
        if (u == u0 || it == 0) {
            if (tid < 256) zbuf[tid] = input_p[b * 256 + tid];
            else           zbuf[tid] = h_tm1[b * 256 + (tid - 256)];
            __syncthreads();
            for (int r = 0; r < 16; ++r) {
                int d = wid * 16 + r;
                const float4* row = reinterpret_cast<const float4*>(W_p_r + (size_t)d * 512);
                const float4* p4  = reinterpret_cast<const float4*>(zbuf);
                float acc = 0.f;
#pragma unroll
                for (int i = 0; i < 4; ++i) {
                    float4 wv = row[i * 32 + lane];
                    float4 pv = p4[i * 32 + lane];
                    acc += wv.x * pv.x + wv.y * pv.y + wv.z * pv.z + wv.w * pv.w;
                }
#pragma unroll
                for (int o = 16; o; o >>= 1) acc += __shfl_xor_sync(0xffffffffu, acc, o);
                if (lane == 0) wg_sh[d] = make_float2(wvec[d], acc + b_p_r[d] + b_q[d]);
            }
            __syncthreads();
        }

        uint32_t* Qcur = (u & 1) ? Qsh1 : Qsh0;
        uint32_t* Qnxt = (u & 1) ? Qsh0 : Qsh1;

        // ---- prefetch: mask for this tile + Q for next unit ----
        int mreg = mask_q[(size_t)b * T_ + it * TT + (tid & 63)];
        bool has_next = (u + 1 < u1);
        float4 pf[8];
        if (has_next) {
            int bn = (u + 1) >> 5, itn = (u + 1) & 31;
            const float4* src = reinterpret_cast<const float4*>(input_q) +
                                (size_t)bn * T_ * 64 + (size_t)itn * TT * 64;
#pragma unroll
            for (int j = 0; j < 8; ++j) pf[j] = src[tid + j * NTHR];
        }

        // ---- MMA: C[64 x 256] = Qtile @ W^T, warp tile m32 x n32 ----
        float c[8][4];
#pragma unroll
        for (int q = 0; q < 8; ++q) { c[q][0] = c[q][1] = c[q][2] = c[q][3] = 0.f; }

#pragma unroll 4
        for (int kc = 0; kc < 16; ++kc) {
            uint32_t a[2][4];
#pragma unroll
            for (int mt = 0; mt < 2; ++mt) {
                int arow = warp_m * 32 + mt * 16 + (lane & 15);
                int acol = kc * 8 + ((lane & 16) ? 4 : 0);
                uint32_t aaddr = (uint32_t)__cvta_generic_to_shared(&Qcur[arow * QSTR + acol]);
                asm volatile("ldmatrix.sync.aligned.m8n8.x4.shared.b16 {%0,%1,%2,%3}, [%4];"
                             : "=r"(a[mt][0]), "=r"(a[mt][1]), "=r"(a[mt][2]), "=r"(a[mt][3])
                             : "r"(aaddr));
            }
#pragma unroll
            for (int np = 0; np < 2; ++np) {
                int row   = warp_n * 32 + np * 16 + (lane & 7) + ((lane & 16) ? 8 : 0);
                int chunk = kc * 2 + ((lane & 8) ? 1 : 0);
                int phys  = chunk ^ (row & 7);
                uint32_t baddr = (uint32_t)__cvta_generic_to_shared(&Wsh[row * 128 + phys * 4]);
                uint32_t b0r, b1r, b2r, b3r;
                asm volatile("ldmatrix.sync.aligned.m8n8.x4.shared.b16 {%0,%1,%2,%3}, [%4];"
                             : "=r"(b0r), "=r"(b1r), "=r"(b2r), "=r"(b3r) : "r"(baddr));
#pragma unroll
                for (int mt = 0; mt < 2; ++mt) {
                    float* c0 = c[mt * 4 + np * 2];
                    float* c1 = c[mt * 4 + np * 2 + 1];
                    asm volatile(
                        "mma.sync.aligned.m16n8k16.row.col.f32.bf16.bf16.f32 "
                        "{%0,%1,%2,%3}, {%4,%5,%6,%7}, {%8,%9}, {%0,%1,%2,%3};"
                        : "+f"(c0[0]), "+f"(c0[1]), "+f"(c0[2]), "+f"(c0[3])
                        : "r"(a[mt][0]), "r"(a[mt][1]), "r"(a[mt][2]), "r"(a[mt][3]),
                          "r"(b0r), "r"(b1r));
                    asm volatile(
                        "mma.sync.aligned.m16n8k16.row.col.f32.bf16.bf16.f32 "
                        "{%0,%1,%2,%3}, {%4,%5,%6,%7}, {%8,%9}, {%0,%1,%2,%3};"
                        : "+f"(c1[0]), "+f"(c1[1]), "+f"(c1[2]), "+f"(c1[3])
                        : "r"(a[mt][0]), "r"(a[mt][1]), "r"(a[mt][2]), "r"(a[mt][3]),
                          "r"(b2r), "r"(b3r));
                }
            }
        }

        // ---- store prefetched tile ----
        if (has_next) {
#pragma unroll
            for (int j = 0; j < 8; ++j) {
                int idx = tid + j * NTHR;
                int row = idx >> 6, c4 = idx & 63;
                __nv_bfloat162 h0 = __floats2bfloat162_rn(pf[j].x, pf[j].y);
                __nv_bfloat162 h1 = __floats2bfloat162_rn(pf[j].z, pf[j].w);
                Qnxt[row * QSTR + c4 * 2]     = *reinterpret_cast<uint32_t*>(&h0);
                Qnxt[row * QSTR + c4 * 2 + 1] = *reinterpret_cast<uint32_t*>(&h1);
            }
        }

        // ---- epilogue: tanh + dot(w), quad reduce ----
#pragma unroll
        for (int mt = 0; mt < 2; ++mt) {
            float p0 = 0.f, p1 = 0.f;
#pragma unroll
            for (int np = 0; np < 2; ++np) {
#pragma unroll
                for (int j = 0; j < 2; ++j) {
                    int n = warp_n * 32 + np * 16 + j * 8 + (lane & 3) * 2;
                    float4 wg = *reinterpret_cast<const float4*>(&wg_sh[n]);
                    float* cc = c[mt * 4 + np * 2 + j];
                    p0 += wg.x * fast_tanh(cc[0] + wg.y) + wg.z * fast_tanh(cc[1] + wg.w);
                    p1 += wg.x * fast_tanh(cc[2] + wg.y) + wg.z * fast_tanh(cc[3] + wg.w);
                }
            }
            p0 += __shfl_xor_sync(0xffffffffu, p0, 1);
            p0 += __shfl_xor_sync(0xffffffffu, p0, 2);
            p1 += __shfl_xor_sync(0xffffffffu, p1, 1);
            p1 += __shfl_xor_sync(0xffffffffu, p1, 2);
            if ((lane & 3) == 0) {
                int row0 = warp_m * 32 + mt * 16 + (lane >> 2);
                ap_sh[row0 * 8 + warp_n]       = p0;
                ap_sh[(row0 + 8) * 8 + warp_n] = p1;
            }
        }
        __syncthreads();   // S1

        // ---- stage 1 ----
        if (tid < TT) {
            const float* ap = &ap_sh[tid * 8];
            float raw = ((ap[0] + ap[1]) + (ap[2] + ap[3])) +
                        ((ap[4] + ap[5]) + (ap[6] + ap[7])) + mb;
            float mflt = (float)mreg;
            float x = fminf(fmaxf(raw, -15.f), 15.f) * mflt;
            float e = __expf(x - 15.f) * mflt;
            e_sh[tid] = e;
            Sth += e;
            Mth = fmaxf(Mth, x);
        }
        __syncthreads();   // S2

        // ---- z update ----
        {
            float a0 = 0.f, a1 = 0.f;
            int tbase = zq * 16;
#pragma unroll
            for (int ttk = 0; ttk < 16; ++ttk) {
                int t = tbase + ttk;
                uint32_t qw = Qcur[t * QSTR + zword];
                __nv_bfloat162 h2 = *reinterpret_cast<__nv_bfloat162*>(&qw);
                float e = e_sh[t];
                a0 += e * __bfloat162float(__low2bfloat16(h2));
                a1 += e * __bfloat162float(__high2bfloat16(h2));
            }
            z0 += a0;
            z1 += a1;
        }
        __syncthreads();   // S3

        // ---- flush at batch end ----
        if (it == 31 || u == u1 - 1) {
            if (tid < TT) {
                float s = Sth, m = Mth;
#pragma unroll
                for (int o = 16; o; o >>= 1) {
                    s += __shfl_xor_sync(0xffffffffu, s, o);
                    m = fmaxf(m, __shfl_xor_sync(0xffffffffu, m, o));
                }
                if (lane == 0) { red[wid * 2] = s; red[wid * 2 + 1] = m; }
            }
            zbuf[zq * 256 + d0]     = z0;
            zbuf[zq * 256 + d0 + 1] = z1;
            __syncthreads();

            int i_lo = cta_of_unit(b * 32);
            int slot = cta - i_lo;
            if (tid < 256) {
                float zt = (zbuf[tid] + zbuf[256 + tid]) + (zbuf[512 + tid] + zbuf[768 + tid]);
                g_pz[(b * 4 + slot) * 256 + tid] = zt;
            }
            if (tid == 0) {
                g_ps[(b * 4 + slot) * 2]     = red[0] + red[2];
                g_ps[(b * 4 + slot) * 2 + 1] = fmaxf(red[1], red[3]);
            }
            Sth = 0.f; Mth = -1e30f; z0 = 0.f; z1 = 0.f;
            __threadfence();
            __syncthreads();
            if (tid == 0) {
                int i_hi = cta_of_unit(b * 32 + 31);
                int count = i_hi - i_lo + 1;
                int old = atomicAdd(&g_cnt[b], 1);
                *flagp = ((old % count) == count - 1) ? count : 0;
            }
            __syncthreads();
            int cc = *flagp;
            if (cc) {
                __threadfence();
                if (tid < 256) {
                    float zt = 0.f, Sp = 0.f, Mg = -1e30f;
#pragma unroll 4
                    for (int s = 0; s < cc; ++s) {
                        zt += __ldcg(&g_pz[(b * 4 + s) * 256 + tid]);
                        Sp += __ldcg(&g_ps[(b * 4 + s) * 2]);
                        Mg = fmaxf(Mg, __ldcg(&g_ps[(b * 4 + s) * 2 + 1]));
                    }
                    float denom = Sp + 1e-6f * __expf(Mg - 15.f);
                    out[b * 512 + tid]       = input_p[b * 256 + tid];
                    out[b * 512 + 256 + tid] = zt / denom;
                }
            }
            __syncthreads();
        }
    }
}

extern "C" void kernel_launch(void* const* d_in, const int* in_sizes, int n_in,
                              void* d_out, int out_size) {
    const float* input_p = (const float*)d_in[0];
    const float* input_q = (const float*)d_in[2];
    const int*   mask_q  = (const int*)d_in[3];
    const float* h_tm1   = (const float*)d_in[4];
    const float* W_p_r   = (const float*)d_in[5];
    const float* b_p_r   = (const float*)d_in[6];
    const float* W_q     = (const float*)d_in[7];
    const float* b_q     = (const float*)d_in[8];
    const float* wv      = (const float*)d_in[9];
    const float* match_b = (const float*)d_in[10];
    float* out = (float*)d_out;

    size_t smemF = (size_t)SMEM_WORDS * 4;
    cudaFuncSetAttribute(kFused, cudaFuncAttributeMaxDynamicSharedMemorySize, (int)smemF);
    kFused<<<GRID, NTHR, smemF>>>(input_q, W_q, wv, match_b, mask_q,
                                  input_p, h_tm1, W_p_r, b_p_r, b_q, out);
}

// round 17
// speedup vs baseline: 1.1186x; 1.0611x over previous
#include <cuda_runtime.h>
#include <cuda_bf16.h>
#include <cstdint>

#define B_ 128
#define T_ 2048
#define TT 64
#define QSTR 132
#define NTHR 512
#define GRID 148
#define UNITS 4096     // 128 batches * 32 tiles

// smem word offsets
#define WSH_OFF 0                          // 32768: W bf16, swizzled
#define Q0_OFF  32768                      // 8448
#define Q1_OFF  (Q0_OFF + TT * QSTR)       // 41216
#define WG_OFF  (Q1_OFF + TT * QSTR)       // 49664: float2 {w,gpr} x256
#define E_OFF   (WG_OFF + 512)             // e[64]
#define AP_OFF  (E_OFF + 64)               // ap[64][8]
#define RED_OFF (AP_OFF + 512)             // 20 words (16 red + flag)
#define ZB_OFF  (RED_OFF + 20)             // zbuf[4][256] / ph[512]
#define SMEM_WORDS (ZB_OFF + 1024)

__device__ float g_pz[B_ * 4 * 256];       // z partial per (batch, slot)
__device__ float g_ps[B_ * 4 * 2];         // {S, M} per (batch, slot)
__device__ int   g_cnt[B_];                // arrival tickets (monotone; used mod count)

__device__ __forceinline__ float fast_tanh(float x) {
    float y;
    asm("tanh.approx.f32 %0, %1;" : "=f"(y) : "f"(x));
    return y;
}

__device__ __forceinline__ int unit_start(int i) {
    return (int)(((long long)i * UNITS) / GRID);
}
__device__ __forceinline__ int cta_of_unit(int u) {
    int i = (int)(((long long)u * GRID) / UNITS);
    while (unit_start(i + 1) <= u) ++i;
    return i;
}

__global__ __launch_bounds__(NTHR, 1)
void kFused(const float* __restrict__ input_q,
            const float* __restrict__ W_q,
            const float* __restrict__ wvec,
            const float* __restrict__ match_b,
            const int* __restrict__ mask_q,
            const float* __restrict__ input_p,
            const float* __restrict__ h_tm1,
            const float* __restrict__ W_p_r,
            const float* __restrict__ b_p_r,
            const float* __restrict__ b_q,
            float* __restrict__ out) {
    extern __shared__ uint32_t sh[];
    uint32_t* Wsh  = sh + WSH_OFF;
    uint32_t* Qsh0 = sh + Q0_OFF;
    uint32_t* Qsh1 = sh + Q1_OFF;
    float2* wg_sh = reinterpret_cast<float2*>(sh + WG_OFF);
    float*  e_sh  = reinterpret_cast<float*>(sh + E_OFF);
    float*  ap_sh = reinterpret_cast<float*>(sh + AP_OFF);
    float*  red   = reinterpret_cast<float*>(sh + RED_OFF);
    int*    flagp = reinterpret_cast<int*>(sh + RED_OFF + 16);
    float*  zbuf  = reinterpret_cast<float*>(sh + ZB_OFF);

    int cta  = blockIdx.x;
    int tid  = threadIdx.x;
    int lane = tid & 31, wid = tid >> 5;
    int u0 = unit_start(cta), u1 = unit_start(cta + 1);

    // ================= Prologue: W_q -> bf16 smem (XOR swizzle) =================
    for (int i = tid; i < 256 * 128; i += NTHR) {
        int n = i >> 7, kw = i & 127;
        float2 f = reinterpret_cast<const float2*>(W_q)[n * 128 + kw];
        __nv_bfloat162 h = __floats2bfloat162_rn(f.x, f.y);
        int phys = (kw >> 2) ^ (n & 7);
        Wsh[n * 128 + phys * 4 + (kw & 3)] = *reinterpret_cast<uint32_t*>(&h);
    }

    const float mb = match_b[0];

    // preload first unit's Q tile
    {
        int b0 = u0 >> 5, it0 = u0 & 31;
        const float4* src = reinterpret_cast<const float4*>(input_q) +
                            (size_t)b0 * T_ * 64 + (size_t)it0 * TT * 64;
        uint32_t* Qdst = (u0 & 1) ? Qsh1 : Qsh0;
#pragma unroll
        for (int j = 0; j < 8; ++j) {
            int idx = tid + j * NTHR;
            float4 f = src[idx];
            int row = idx >> 6, c4 = idx & 63;
            __nv_bfloat162 h0 = __floats2bfloat162_rn(f.x, f.y);
            __nv_bfloat162 h1 = __floats2bfloat162_rn(f.z, f.w);
            Qdst[row * QSTR + c4 * 2]     = *reinterpret_cast<uint32_t*>(&h0);
            Qdst[row * QSTR + c4 * 2 + 1] = *reinterpret_cast<uint32_t*>(&h1);
        }
    }
    __syncthreads();

    // ================= Unit loop =================
    int warp_m = wid & 1;
    int warp_n = wid >> 1;
    int zq = wid >> 2;
    int d0 = (tid & 127) * 2;
    int zword = tid & 127;

    float Sth = 0.f, Mth = -1e30f;
    float z0 = 0.f, z1 = 0.f;

    for (int u = u0; u < u1; ++u) {
        int b  = u >> 5;
        int it = u & 31;

        // ---- batch setup (gpr) at batch entry ----
        if (u == u0 || it == 0) {
            if (tid < 256) zbuf[tid] = input_p[b * 256 + tid];
            else           zbuf[tid] = h_tm1[b * 256 + (tid - 256)];
            __syncthreads();
            for (int r = 0; r < 16; ++r) {
                int d = wid * 16 + r;
                const float4* row = reinterpret_cast<const float4*>(W_p_r + (size_t)d * 512);
                const float4* p4  = reinterpret_cast<const float4*>(zbuf);
                float acc = 0.f;
#pragma unroll
                for (int i = 0; i < 4; ++i) {
                    float4 wv = row[i * 32 + lane];
                    float4 pv = p4[i * 32 + lane];
                    acc += wv.x * pv.x + wv.y * pv.y + wv.z * pv.z + wv.w * pv.w;
                }
#pragma unroll
                for (int o = 16; o; o >>= 1) acc += __shfl_xor_sync(0xffffffffu, acc, o);
                if (lane == 0) wg_sh[d] = make_float2(wvec[d], acc + b_p_r[d] + b_q[d]);
            }
            __syncthreads();
        }

        uint32_t* Qcur = (u & 1) ? Qsh1 : Qsh0;
        uint32_t* Qnxt = (u & 1) ? Qsh0 : Qsh1;

        // ---- prefetch: mask + Q chunk1 (rows 0..31) of next unit ----
        int mreg = mask_q[(size_t)b * T_ + it * TT + (tid & 63)];
        bool has_next = (u + 1 < u1);
        const float4* srcn = nullptr;
        float4 pf1[4];
        if (has_next) {
            int bn = (u + 1) >> 5, itn = (u + 1) & 31;
            srcn = reinterpret_cast<const float4*>(input_q) +
                   (size_t)bn * T_ * 64 + (size_t)itn * TT * 64;
#pragma unroll
            for (int j = 0; j < 4; ++j) pf1[j] = srcn[tid + j * NTHR];
        }

        // ---- MMA: C[64 x 256] = Qtile @ W^T, warp tile m32 x n32 ----
        float c[8][4];
#pragma unroll
        for (int q = 0; q < 8; ++q) { c[q][0] = c[q][1] = c[q][2] = c[q][3] = 0.f; }

#pragma unroll 8
        for (int kc = 0; kc < 16; ++kc) {
            uint32_t a[2][4];
#pragma unroll
            for (int mt = 0; mt < 2; ++mt) {
                int arow = warp_m * 32 + mt * 16 + (lane & 15);
                int acol = kc * 8 + ((lane & 16) ? 4 : 0);
                uint32_t aaddr = (uint32_t)__cvta_generic_to_shared(&Qcur[arow * QSTR + acol]);
                asm volatile("ldmatrix.sync.aligned.m8n8.x4.shared.b16 {%0,%1,%2,%3}, [%4];"
                             : "=r"(a[mt][0]), "=r"(a[mt][1]), "=r"(a[mt][2]), "=r"(a[mt][3])
                             : "r"(aaddr));
            }
#pragma unroll
            for (int np = 0; np < 2; ++np) {
                int row   = warp_n * 32 + np * 16 + (lane & 7) + ((lane & 16) ? 8 : 0);
                int chunk = kc * 2 + ((lane & 8) ? 1 : 0);
                int phys  = chunk ^ (row & 7);
                uint32_t baddr = (uint32_t)__cvta_generic_to_shared(&Wsh[row * 128 + phys * 4]);
                uint32_t b0r, b1r, b2r, b3r;
                asm volatile("ldmatrix.sync.aligned.m8n8.x4.shared.b16 {%0,%1,%2,%3}, [%4];"
                             : "=r"(b0r), "=r"(b1r), "=r"(b2r), "=r"(b3r) : "r"(baddr));
#pragma unroll
                for (int mt = 0; mt < 2; ++mt) {
                    float* c0 = c[mt * 4 + np * 2];
                    float* c1 = c[mt * 4 + np * 2 + 1];
                    asm volatile(
                        "mma.sync.aligned.m16n8k16.row.col.f32.bf16.bf16.f32 "
                        "{%0,%1,%2,%3}, {%4,%5,%6,%7}, {%8,%9}, {%0,%1,%2,%3};"
                        : "+f"(c0[0]), "+f"(c0[1]), "+f"(c0[2]), "+f"(c0[3])
                        : "r"(a[mt][0]), "r"(a[mt][1]), "r"(a[mt][2]), "r"(a[mt][3]),
                          "r"(b0r), "r"(b1r));
                    asm volatile(
                        "mma.sync.aligned.m16n8k16.row.col.f32.bf16.bf16.f32 "
                        "{%0,%1,%2,%3}, {%4,%5,%6,%7}, {%8,%9}, {%0,%1,%2,%3};"
                        : "+f"(c1[0]), "+f"(c1[1]), "+f"(c1[2]), "+f"(c1[3])
                        : "r"(a[mt][0]), "r"(a[mt][1]), "r"(a[mt][2]), "r"(a[mt][3]),
                          "r"(b2r), "r"(b3r));
                }
            }
        }

        // ---- STS chunk1, issue LDG chunk2 (latency covered by epilogue) ----
        float4 pf2[4];
        if (has_next) {
#pragma unroll
            for (int j = 0; j < 4; ++j) {
                int idx = tid + j * NTHR;
                int row = idx >> 6, c4 = idx & 63;
                __nv_bfloat162 h0 = __floats2bfloat162_rn(pf1[j].x, pf1[j].y);
                __nv_bfloat162 h1 = __floats2bfloat162_rn(pf1[j].z, pf1[j].w);
                Qnxt[row * QSTR + c4 * 2]     = *reinterpret_cast<uint32_t*>(&h0);
                Qnxt[row * QSTR + c4 * 2 + 1] = *reinterpret_cast<uint32_t*>(&h1);
            }
#pragma unroll
            for (int j = 0; j < 4; ++j) pf2[j] = srcn[tid + (j + 4) * NTHR];
        }

        // ---- epilogue: tanh + dot(w), quad reduce ----
#pragma unroll
        for (int mt = 0; mt < 2; ++mt) {
            float p0 = 0.f, p1 = 0.f;
#pragma unroll
            for (int np = 0; np < 2; ++np) {
#pragma unroll
                for (int j = 0; j < 2; ++j) {
                    int n = warp_n * 32 + np * 16 + j * 8 + (lane & 3) * 2;
                    float4 wg = *reinterpret_cast<const float4*>(&wg_sh[n]);
                    float* cc = c[mt * 4 + np * 2 + j];
                    p0 += wg.x * fast_tanh(cc[0] + wg.y) + wg.z * fast_tanh(cc[1] + wg.w);
                    p1 += wg.x * fast_tanh(cc[2] + wg.y) + wg.z * fast_tanh(cc[3] + wg.w);
                }
            }
            p0 += __shfl_xor_sync(0xffffffffu, p0, 1);
            p0 += __shfl_xor_sync(0xffffffffu, p0, 2);
            p1 += __shfl_xor_sync(0xffffffffu, p1, 1);
            p1 += __shfl_xor_sync(0xffffffffu, p1, 2);
            if ((lane & 3) == 0) {
                int row0 = warp_m * 32 + mt * 16 + (lane >> 2);
                ap_sh[row0 * 8 + warp_n]       = p0;
                ap_sh[(row0 + 8) * 8 + warp_n] = p1;
            }
        }

        // ---- STS chunk2 ----
        if (has_next) {
#pragma unroll
            for (int j = 0; j < 4; ++j) {
                int idx = tid + (j + 4) * NTHR;
                int row = idx >> 6, c4 = idx & 63;
                __nv_bfloat162 h0 = __floats2bfloat162_rn(pf2[j].x, pf2[j].y);
                __nv_bfloat162 h1 = __floats2bfloat162_rn(pf2[j].z, pf2[j].w);
                Qnxt[row * QSTR + c4 * 2]     = *reinterpret_cast<uint32_t*>(&h0);
                Qnxt[row * QSTR + c4 * 2 + 1] = *reinterpret_cast<uint32_t*>(&h1);
            }
        }
        __syncthreads();   // S1

        // ---- stage 1 (tid<64) ----
        if (tid < TT) {
            const float4* ap4 = reinterpret_cast<const float4*>(&ap_sh[tid * 8]);
            float4 apa = ap4[0], apb = ap4[1];
            float raw = ((apa.x + apa.y) + (apa.z + apa.w)) +
                        ((apb.x + apb.y) + (apb.z + apb.w)) + mb;
            float mflt = (float)mreg;
            float x = fminf(fmaxf(raw, -15.f), 15.f) * mflt;
            float e = __expf(x - 15.f) * mflt;
            e_sh[tid] = e;
            Sth += e;
            Mth = fmaxf(Mth, x);
        }
        __syncthreads();   // S2

        // ---- z update ----
        {
            float a0 = 0.f, a1 = 0.f;
            int tbase = zq * 16;
#pragma unroll
            for (int ttk = 0; ttk < 16; ++ttk) {
                int t = tbase + ttk;
                uint32_t qw = Qcur[t * QSTR + zword];
                __nv_bfloat162 h2 = *reinterpret_cast<__nv_bfloat162*>(&qw);
                float e = e_sh[t];
                a0 += e * __bfloat162float(__low2bfloat16(h2));
                a1 += e * __bfloat162float(__high2bfloat16(h2));
            }
            z0 += a0;
            z1 += a1;
        }
        __syncthreads();   // S3

        // ---- flush at batch end ----
        if (it == 31 || u == u1 - 1) {
            if (tid < TT) {
                float s = Sth, m = Mth;
#pragma unroll
                for (int o = 16; o; o >>= 1) {
                    s += __shfl_xor_sync(0xffffffffu, s, o);
                    m = fmaxf(m, __shfl_xor_sync(0xffffffffu, m, o));
                }
                if (lane == 0) { red[wid * 2] = s; red[wid * 2 + 1] = m; }
            }
            zbuf[zq * 256 + d0]     = z0;
            zbuf[zq * 256 + d0 + 1] = z1;
            __syncthreads();

            int i_lo = cta_of_unit(b * 32);
            int slot = cta - i_lo;
            if (tid < 256) {
                float zt = (zbuf[tid] + zbuf[256 + tid]) + (zbuf[512 + tid] + zbuf[768 + tid]);
                g_pz[(b * 4 + slot) * 256 + tid] = zt;
            }
            if (tid == 0) {
                g_ps[(b * 4 + slot) * 2]     = red[0] + red[2];
                g_ps[(b * 4 + slot) * 2 + 1] = fmaxf(red[1], red[3]);
            }
            Sth = 0.f; Mth = -1e30f; z0 = 0.f; z1 = 0.f;
            __threadfence();
            __syncthreads();
            if (tid == 0) {
                int i_hi = cta_of_unit(b * 32 + 31);
                int count = i_hi - i_lo + 1;
                int old = atomicAdd(&g_cnt[b], 1);
                *flagp = ((old % count) == count - 1) ? count : 0;
            }
            __syncthreads();
            int cc = *flagp;
            if (cc) {
                __threadfence();
                if (tid < 256) {
                    float zt = 0.f, Sp = 0.f, Mg = -1e30f;
#pragma unroll 4
                    for (int s = 0; s < cc; ++s) {
                        zt += __ldcg(&g_pz[(b * 4 + s) * 256 + tid]);
                        Sp += __ldcg(&g_ps[(b * 4 + s) * 2]);
                        Mg = fmaxf(Mg, __ldcg(&g_ps[(b * 4 + s) * 2 + 1]));
                    }
                    float denom = Sp + 1e-6f * __expf(Mg - 15.f);
                    out[b * 512 + tid]       = input_p[b * 256 + tid];
                    out[b * 512 + 256 + tid] = zt / denom;
                }
            }
            __syncthreads();
        }
    }
}

extern "C" void kernel_launch(void* const* d_in, const int* in_sizes, int n_in,
                              void* d_out, int out_size) {
    const float* input_p = (const float*)d_in[0];
    const float* input_q = (const float*)d_in[2];
    const int*   mask_q  = (const int*)d_in[3];
    const float* h_tm1   = (const float*)d_in[4];
    const float* W_p_r   = (const float*)d_in[5];
    const float* b_p_r   = (const float*)d_in[6];
    const float* W_q     = (const float*)d_in[7];
    const float* b_q     = (const float*)d_in[8];
    const float* wv      = (const float*)d_in[9];
    const float* match_b = (const float*)d_in[10];
    float* out = (float*)d_out;

    size_t smemF = (size_t)SMEM_WORDS * 4;
    cudaFuncSetAttribute(kFused, cudaFuncAttributeMaxDynamicSharedMemorySize, (int)smemF);
    kFused<<<GRID, NTHR, smemF>>>(input_q, W_q, wv, match_b, mask_q,
                                  input_p, h_tm1, W_p_r, b_p_r, b_q, out);
}